// round 11
// baseline (speedup 1.0000x reference)
#include <cuda_runtime.h>
#include <cuda_bf16.h>
#include <cstdint>

// InverseAvgPool1d, K=8 -> half=4, s=9.
// S'[t] = 8*A[t] - 8*x0*[t%9 <= 4],  A[t] = stride-9 prefix sum of x.
// out[t] = S'[t] - S'[t-1]   (S'[-1] = 0).  Correction folded into writeback.
//
// 2 rows per CTA: interleaved staging of both rows (one 32KB read burst,
// MLP~8), sequential per-row compute (single a[] buffer, lane-private =>
// no barrier between gather and writeback), interleaved 2-stream diff pass.

#define ROW_T 4096
#define NWARP 9
#define NTHREADS (NWARP * 32)   // 288
#define PER_LANE 15             // 32*15 = 480 slots; real max 456

__global__ __launch_bounds__(NTHREADS)
void inv_avgpool_kernel(const float* __restrict__ x, float* __restrict__ out) {
    __shared__ __align__(16) float s[2][ROW_T];

    const int tid = threadIdx.x;
    const int lane = tid & 31;
    const int r = tid >> 5;                  // residue chain 0..8

    const size_t row0 = (size_t)blockIdx.x * 2;
    const float4* __restrict__ xr0 = (const float4*)(x + row0 * ROW_T);
    const float4* __restrict__ xr1 = (const float4*)(x + (row0 + 1) * ROW_T);

    // x0 of both rows via global broadcast
    const float x0a = __ldg(x + row0 * ROW_T);
    const float x0b = __ldg(x + (row0 + 1) * ROW_T);

    // 1) interleaved coalesced stage of both rows (8 independent LDG.128/thread)
    #pragma unroll
    for (int q = tid; q < ROW_T / 4; q += NTHREADS) {
        float4 v0 = __ldcs(xr0 + q);
        float4 v1 = __ldcs(xr1 + q);
        ((float4*)s[0])[q] = v0;
        ((float4*)s[1])[q] = v1;
    }
    __syncthreads();

    const int base = r + 135 * lane;         // lanes 0..29: base+126 <= 4049
    const int lim30 = (r == 0) ? 6 : 5;      // lane 30 valid count

    // 2) per-row gather/scan/writeback (all slots lane-private; no barriers)
    #pragma unroll 1
    for (int rr = 0; rr < 2; rr++) {
        float* sr = s[rr];
        const float x0 = rr ? x0b : x0a;

        float a[PER_LANE];
        float run = 0.f;
        if (lane < 30) {
            #pragma unroll
            for (int j = 0; j < PER_LANE; j++) { run += sr[base + 9 * j]; a[j] = run; }
        } else if (lane == 30) {
            #pragma unroll
            for (int j = 0; j < PER_LANE; j++) {
                if (j < lim30) run += sr[base + 9 * j];
                a[j] = run;
            }
        }

        float incl = run;
        #pragma unroll
        for (int off = 1; off < 32; off <<= 1) {
            float up = __shfl_up_sync(0xffffffffu, incl, off);
            if (lane >= off) incl += up;
        }
        float e8 = 8.f * (incl - run);
        if (r <= 4) e8 -= 8.f * x0;          // fold x0 correction into S'

        if (lane < 30) {
            #pragma unroll
            for (int j = 0; j < PER_LANE; j++) sr[base + 9 * j] = fmaf(8.f, a[j], e8);
        } else if (lane == 30) {
            #pragma unroll
            for (int j = 0; j < PER_LANE; j++)
                if (j < lim30) sr[base + 9 * j] = fmaf(8.f, a[j], e8);
        }
    }
    __syncthreads();

    // 3) interleaved diff pass: out[t] = S'[t] - S'[t-1], streaming stores
    float4* __restrict__ o0 = (float4*)(out + row0 * ROW_T);
    float4* __restrict__ o1 = (float4*)(out + (row0 + 1) * ROW_T);
    #pragma unroll
    for (int q = tid; q < ROW_T / 4; q += NTHREADS) {
        float4 B0 = ((const float4*)s[0])[q];
        float4 B1 = ((const float4*)s[1])[q];
        float p0 = __shfl_up_sync(0xffffffffu, B0.w, 1);
        float p1 = __shfl_up_sync(0xffffffffu, B1.w, 1);
        if (lane == 0) {
            p0 = (q == 0) ? 0.f : s[0][4 * q - 1];
            p1 = (q == 0) ? 0.f : s[1][4 * q - 1];
        }
        float4 a0, a1;
        a0.x = B0.x - p0;  a0.y = B0.y - B0.x;
        a0.z = B0.z - B0.y; a0.w = B0.w - B0.z;
        a1.x = B1.x - p1;  a1.y = B1.y - B1.x;
        a1.z = B1.z - B1.y; a1.w = B1.w - B1.z;
        __stcs(o0 + q, a0);
        __stcs(o1 + q, a1);
    }
}

extern "C" void kernel_launch(void* const* d_in, const int* in_sizes, int n_in,
                              void* d_out, int out_size) {
    const float* x = (const float*)d_in[0];
    float* out = (float*)d_out;
    const int rows = in_sizes[0] / ROW_T;   // 16384
    inv_avgpool_kernel<<<rows / 2, NTHREADS>>>(x, out);
}

// round 12
// speedup vs baseline: 1.2035x; 1.2035x over previous
#include <cuda_runtime.h>
#include <cuda_bf16.h>
#include <cstdint>

// InverseAvgPool1d, K=8 -> half=4, s=9.
// S'[t] = 8*A[t] - 8*x0*[t%9 <= 4],  A[t] = stride-9 prefix sum of x.
// out[t] = S'[t] - S'[t-1]   (S'[-1] = 0).  Correction folded into writeback.
//
// One row per CTA, 9 warps = 9 residue chains, 31 regs / 16KB smem
// => 7 CTAs/SM (2016/2048 threads). Gather/writeback slots are lane-private
// => no barrier between gather and writeback. Streaming loads, write-through
// stores (keep L2 slices for the read stream).

#define ROW_T 4096
#define NWARP 9
#define NTHREADS (NWARP * 32)   // 288
#define PER_LANE 15             // 32*15 = 480 slots; real max 456

__global__ __launch_bounds__(NTHREADS, 7)
void inv_avgpool_kernel(const float* __restrict__ x, float* __restrict__ out) {
    __shared__ __align__(16) float s[ROW_T];

    const int tid = threadIdx.x;
    const int lane = tid & 31;
    const int r = tid >> 5;                  // residue chain 0..8

    const size_t row = blockIdx.x;
    const float4* __restrict__ xr = (const float4*)(x + row * ROW_T);
    float4* __restrict__ outr = (float4*)(out + row * ROW_T);

    // x0 via global broadcast (no smem dependency on s[0])
    const float x0 = __ldg(x + row * ROW_T);

    // 1) coalesced stage, streaming loads
    #pragma unroll
    for (int q = tid; q < ROW_T / 4; q += NTHREADS) {
        ((float4*)s)[q] = __ldcs(xr + q);
    }
    __syncthreads();

    const int base = r + 135 * lane;         // lanes 0..29: base+126 <= 4049
    const int lim30 = (r == 0) ? 6 : 5;      // lane 30 valid count

    // 2) gather: lane l accumulates chain slots [15l, 15l+15) (lane-private)
    float a[PER_LANE];
    float run = 0.f;
    if (lane < 30) {
        #pragma unroll
        for (int j = 0; j < PER_LANE; j++) { run += s[base + 9 * j]; a[j] = run; }
    } else if (lane == 30) {
        #pragma unroll
        for (int j = 0; j < PER_LANE; j++) {
            if (j < lim30) run += s[base + 9 * j];
            a[j] = run;
        }
    }

    // 3) warp scan over lane totals -> exclusive carry (warp-synchronous)
    float incl = run;
    #pragma unroll
    for (int off = 1; off < 32; off <<= 1) {
        float up = __shfl_up_sync(0xffffffffu, incl, off);
        if (lane >= off) incl += up;
    }
    float e8 = 8.f * (incl - run);
    if (r <= 4) e8 -= 8.f * x0;              // fold x0 correction into S'

    // 4) writeback S' in place — same lane-private slots, no barrier needed
    if (lane < 30) {
        #pragma unroll
        for (int j = 0; j < PER_LANE; j++) s[base + 9 * j] = fmaf(8.f, a[j], e8);
    } else if (lane == 30) {
        #pragma unroll
        for (int j = 0; j < PER_LANE; j++)
            if (j < lim30) s[base + 9 * j] = fmaf(8.f, a[j], e8);
    }
    __syncthreads();

    // 5) diff pass: out[t] = S'[t] - S'[t-1], write-through stores
    #pragma unroll
    for (int q = tid; q < ROW_T / 4; q += NTHREADS) {
        float4 B = ((const float4*)s)[q];
        float prevw = __shfl_up_sync(0xffffffffu, B.w, 1);
        if (lane == 0) prevw = (q == 0) ? 0.f : s[4 * q - 1];
        float4 o;
        o.x = B.x - prevw;
        o.y = B.y - B.x;
        o.z = B.z - B.y;
        o.w = B.w - B.z;
        __stwt(outr + q, o);
    }
}

extern "C" void kernel_launch(void* const* d_in, const int* in_sizes, int n_in,
                              void* d_out, int out_size) {
    const float* x = (const float*)d_in[0];
    float* out = (float*)d_out;
    const int rows = in_sizes[0] / ROW_T;   // 16384
    inv_avgpool_kernel<<<rows, NTHREADS>>>(x, out);
}

// round 13
// speedup vs baseline: 1.2373x; 1.0281x over previous
#include <cuda_runtime.h>
#include <cuda_bf16.h>
#include <cstdint>

// InverseAvgPool1d, K=8 -> half=4, s=9.
// S'[t] = 8*A[t] - 8*x0*[t%9 <= 4],  A[t] = stride-9 prefix sum of x.
// out[t] = S'[t] - S'[t-1]   (S'[-1] = 0).  Correction folded into writeback.
//
// One row per CTA, 9 warps = 9 residue chains, 31 regs / 16KB smem
// => 7 CTAs/SM (2016 threads). Gather/writeback slots are lane-private
// => no barrier between gather and writeback. Streaming loads + evict-first
// stores (__stcs; write-through measured slower).

#define ROW_T 4096
#define NWARP 9
#define NTHREADS (NWARP * 32)   // 288
#define PER_LANE 15             // 32*15 = 480 slots; real max 456

__global__ __launch_bounds__(NTHREADS, 7)
void inv_avgpool_kernel(const float* __restrict__ x, float* __restrict__ out) {
    __shared__ __align__(16) float s[ROW_T];

    const int tid = threadIdx.x;
    const int lane = tid & 31;
    const int r = tid >> 5;                  // residue chain 0..8

    const size_t row = blockIdx.x;
    const float4* __restrict__ xr = (const float4*)(x + row * ROW_T);
    float4* __restrict__ outr = (float4*)(out + row * ROW_T);

    // x0 via global broadcast (no smem dependency on s[0])
    const float x0 = __ldg(x + row * ROW_T);

    // 1) coalesced stage, streaming loads
    #pragma unroll
    for (int q = tid; q < ROW_T / 4; q += NTHREADS) {
        ((float4*)s)[q] = __ldcs(xr + q);
    }
    __syncthreads();

    const int base = r + 135 * lane;         // lanes 0..29: base+126 <= 4049
    const int lim30 = (r == 0) ? 6 : 5;      // lane 30 valid count

    // 2) gather: lane l accumulates chain slots [15l, 15l+15) (lane-private)
    float a[PER_LANE];
    float run = 0.f;
    if (lane < 30) {
        #pragma unroll
        for (int j = 0; j < PER_LANE; j++) { run += s[base + 9 * j]; a[j] = run; }
    } else if (lane == 30) {
        #pragma unroll
        for (int j = 0; j < PER_LANE; j++) {
            if (j < lim30) run += s[base + 9 * j];
            a[j] = run;
        }
    }

    // 3) warp scan over lane totals -> exclusive carry (warp-synchronous)
    float incl = run;
    #pragma unroll
    for (int off = 1; off < 32; off <<= 1) {
        float up = __shfl_up_sync(0xffffffffu, incl, off);
        if (lane >= off) incl += up;
    }
    float e8 = 8.f * (incl - run);
    if (r <= 4) e8 -= 8.f * x0;              // fold x0 correction into S'

    // 4) writeback S' in place — same lane-private slots, no barrier needed
    if (lane < 30) {
        #pragma unroll
        for (int j = 0; j < PER_LANE; j++) s[base + 9 * j] = fmaf(8.f, a[j], e8);
    } else if (lane == 30) {
        #pragma unroll
        for (int j = 0; j < PER_LANE; j++)
            if (j < lim30) s[base + 9 * j] = fmaf(8.f, a[j], e8);
    }
    __syncthreads();

    // 5) diff pass: out[t] = S'[t] - S'[t-1], evict-first streaming stores
    #pragma unroll
    for (int q = tid; q < ROW_T / 4; q += NTHREADS) {
        float4 B = ((const float4*)s)[q];
        float prevw = __shfl_up_sync(0xffffffffu, B.w, 1);
        if (lane == 0) prevw = (q == 0) ? 0.f : s[4 * q - 1];
        float4 o;
        o.x = B.x - prevw;
        o.y = B.y - B.x;
        o.z = B.z - B.y;
        o.w = B.w - B.z;
        __stcs(outr + q, o);
    }
}

extern "C" void kernel_launch(void* const* d_in, const int* in_sizes, int n_in,
                              void* d_out, int out_size) {
    const float* x = (const float*)d_in[0];
    float* out = (float*)d_out;
    const int rows = in_sizes[0] / ROW_T;   // 16384
    inv_avgpool_kernel<<<rows, NTHREADS>>>(x, out);
}